// round 1
// baseline (speedup 1.0000x reference)
#include <cuda_runtime.h>
#include <cstdint>

// Problem dims (fixed per reference setup_inputs)
#define BB 8
#define SS 2048
#define DD 512
#define II 2048
#define MM (BB*SS)   // 16384 rows (b*S+s)

// GEMM tiling
#define TM 128
#define TN 32
#define TK 32
#define LN3 1.0986122886681098f

// Scratch: adaptive_alpha and drive, [M, I] each (128 MiB each)
__device__ float g_a[(size_t)MM * II];
__device__ float g_c[(size_t)MM * II];

__device__ __forceinline__ float sigmoidf_(float v) {
    return 1.0f / (1.0f + __expf(-v));
}

__device__ __forceinline__ float f2tf32(float x) {
    uint32_t u;
    asm("cvt.rna.tf32.f32 %0, %1;" : "=r"(u) : "f"(x));
    return __uint_as_float(u);
}

__device__ __forceinline__ void mma_tf32(float* d, const uint32_t* a, const uint32_t* b) {
    asm volatile(
        "mma.sync.aligned.m16n8k8.row.col.f32.tf32.tf32.f32 "
        "{%0,%1,%2,%3}, {%4,%5,%6,%7}, {%8,%9}, {%0,%1,%2,%3};\n"
        : "+f"(d[0]), "+f"(d[1]), "+f"(d[2]), "+f"(d[3])
        : "r"(a[0]), "r"(a[1]), "r"(a[2]), "r"(a[3]),
          "r"(b[0]), "r"(b[1]));
}

// Fused epilogue for one (m, i) element given raw pa, pi accumulators
__device__ __forceinline__ void emit_ac(int m, int i, float pa, float pi,
                                        const float* __restrict__ ba,
                                        const float* __restrict__ bi,
                                        const float* __restrict__ gate) {
    pa += __ldg(&ba[i]);
    pi += __ldg(&bi[i]);
    float rg = sigmoidf_(pa);                 // reset gate
    float ig = sigmoidf_(pi);                 // input gate
    float al = sigmoidf_(__ldg(&gate[i]));    // alpha
    float aa = al * __expf(-LN3 * rg);        // adaptive alpha = alpha / 3^rg
    float dr = sqrtf(fmaxf(1.0f - aa * aa, 0.0f)) * (ig * pi);
    size_t o = (size_t)m * II + i;
    g_a[o] = aa;
    g_c[o] = dr;
}

// GEMM: P = x @ W^T for both Wa and Wi simultaneously (same x tile reused),
// fused with the gate/drive elementwise epilogue.
// grid: (MM/TM, II/TN), block: 256 threads (8 warps, 4x2 warp grid)
__global__ void __launch_bounds__(256, 1) gemm_fused_kernel(
    const float* __restrict__ x, const float* __restrict__ Wa,
    const float* __restrict__ ba, const float* __restrict__ Wi,
    const float* __restrict__ bi, const float* __restrict__ gate)
{
    __shared__ float xs[TM][TK + 4];   // pad 4 -> conflict-free frag loads
    __shared__ float was[TN][TK + 4];
    __shared__ float wis[TN][TK + 4];

    const int tid  = threadIdx.x;
    const int lane = tid & 31;
    const int warp = tid >> 5;
    const int wm   = warp >> 1;   // 0..3 -> 32-row slices
    const int wn   = warp & 1;    // 0..1 -> 16-col slices
    const int g    = lane >> 2;   // groupID 0..7
    const int tg   = lane & 3;    // threadID_in_group 0..3

    const int m_blk = blockIdx.x * TM;
    const int n_blk = blockIdx.y * TN;

    float accA[2][2][4];
    float accB[2][2][4];
    #pragma unroll
    for (int a = 0; a < 2; a++)
        #pragma unroll
        for (int b = 0; b < 2; b++)
            #pragma unroll
            for (int r = 0; r < 4; r++) { accA[a][b][r] = 0.0f; accB[a][b][r] = 0.0f; }

    for (int k0 = 0; k0 < DD; k0 += TK) {
        // ---- load x tile: 128x32 floats = 1024 float4, 4 per thread ----
        #pragma unroll
        for (int j = 0; j < 4; j++) {
            int idx = tid + j * 256;
            int row = idx >> 3;
            int c4  = (idx & 7) * 4;
            float4 v = *reinterpret_cast<const float4*>(
                &x[(size_t)(m_blk + row) * DD + k0 + c4]);
            v.x = f2tf32(v.x); v.y = f2tf32(v.y);
            v.z = f2tf32(v.z); v.w = f2tf32(v.w);
            *reinterpret_cast<float4*>(&xs[row][c4]) = v;
        }
        // ---- load Wa, Wi tiles: 32x32 floats = 256 float4, 1 per thread ----
        {
            int row = tid >> 3;
            int c4  = (tid & 7) * 4;
            float4 va = *reinterpret_cast<const float4*>(
                &Wa[(size_t)(n_blk + row) * DD + k0 + c4]);
            va.x = f2tf32(va.x); va.y = f2tf32(va.y);
            va.z = f2tf32(va.z); va.w = f2tf32(va.w);
            *reinterpret_cast<float4*>(&was[row][c4]) = va;

            float4 vi = *reinterpret_cast<const float4*>(
                &Wi[(size_t)(n_blk + row) * DD + k0 + c4]);
            vi.x = f2tf32(vi.x); vi.y = f2tf32(vi.y);
            vi.z = f2tf32(vi.z); vi.w = f2tf32(vi.w);
            *reinterpret_cast<float4*>(&wis[row][c4]) = vi;
        }
        __syncthreads();

        #pragma unroll
        for (int kk = 0; kk < TK; kk += 8) {
            uint32_t afr[2][4];
            #pragma unroll
            for (int mt = 0; mt < 2; mt++) {
                int r0 = wm * 32 + mt * 16 + g;
                afr[mt][0] = __float_as_uint(xs[r0    ][kk + tg    ]);
                afr[mt][1] = __float_as_uint(xs[r0 + 8][kk + tg    ]);
                afr[mt][2] = __float_as_uint(xs[r0    ][kk + tg + 4]);
                afr[mt][3] = __float_as_uint(xs[r0 + 8][kk + tg + 4]);
            }
            uint32_t bfA[2][2], bfB[2][2];
            #pragma unroll
            for (int nt = 0; nt < 2; nt++) {
                int rn = wn * 16 + nt * 8 + g;
                bfA[nt][0] = __float_as_uint(was[rn][kk + tg    ]);
                bfA[nt][1] = __float_as_uint(was[rn][kk + tg + 4]);
                bfB[nt][0] = __float_as_uint(wis[rn][kk + tg    ]);
                bfB[nt][1] = __float_as_uint(wis[rn][kk + tg + 4]);
            }
            #pragma unroll
            for (int mt = 0; mt < 2; mt++) {
                #pragma unroll
                for (int nt = 0; nt < 2; nt++) {
                    mma_tf32(accA[mt][nt], afr[mt], bfA[nt]);
                    mma_tf32(accB[mt][nt], afr[mt], bfB[nt]);
                }
            }
        }
        __syncthreads();
    }

    // ---- fused epilogue: pa/pi -> adaptive_alpha, drive ----
    #pragma unroll
    for (int mt = 0; mt < 2; mt++) {
        #pragma unroll
        for (int nt = 0; nt < 2; nt++) {
            int m0 = m_blk + wm * 32 + mt * 16 + g;
            int i0 = n_blk + wn * 16 + nt * 8 + 2 * tg;
            emit_ac(m0,     i0,     accA[mt][nt][0], accB[mt][nt][0], ba, bi, gate);
            emit_ac(m0,     i0 + 1, accA[mt][nt][1], accB[mt][nt][1], ba, bi, gate);
            emit_ac(m0 + 8, i0,     accA[mt][nt][2], accB[mt][nt][2], ba, bi, gate);
            emit_ac(m0 + 8, i0 + 1, accA[mt][nt][3], accB[mt][nt][3], ba, bi, gate);
        }
    }
}

// Sequential scan over S for each (b, i) channel. Loads across s are
// independent -> prefetch next chunk of 8 while FMA-chaining current chunk.
// grid: (B*I)/128 = 128 CTAs, 128 threads each; warp = 32 consecutive i -> coalesced.
__global__ void __launch_bounds__(128, 1) scan_kernel(float* __restrict__ out)
{
    int idx = blockIdx.x * 128 + threadIdx.x;   // 0..16383
    int b = idx >> 11;        // / 2048
    int i = idx & (II - 1);
    size_t base = (size_t)b * SS * II + i;
    const float* ap = g_a + base;
    const float* cp = g_c + base;
    float* op = out + base;

    float h = 0.0f;
    float av[8], cv[8], av2[8], cv2[8];
    #pragma unroll
    for (int j = 0; j < 8; j++) {
        av[j] = ap[(size_t)j * II];
        cv[j] = cp[(size_t)j * II];
    }
    for (int s = 0; s < SS; s += 8) {
        if (s + 8 < SS) {
            #pragma unroll
            for (int j = 0; j < 8; j++) {
                av2[j] = ap[(size_t)(s + 8 + j) * II];
                cv2[j] = cp[(size_t)(s + 8 + j) * II];
            }
        }
        #pragma unroll
        for (int j = 0; j < 8; j++) {
            h = fmaf(av[j], h, cv[j]);
            op[(size_t)(s + j) * II] = h;
        }
        #pragma unroll
        for (int j = 0; j < 8; j++) { av[j] = av2[j]; cv[j] = cv2[j]; }
    }
}

extern "C" void kernel_launch(void* const* d_in, const int* in_sizes, int n_in,
                              void* d_out, int out_size)
{
    const float* x    = (const float*)d_in[0];
    const float* Wa   = (const float*)d_in[1];
    const float* ba   = (const float*)d_in[2];
    const float* Wi   = (const float*)d_in[3];
    const float* bi   = (const float*)d_in[4];
    const float* gate = (const float*)d_in[5];
    float* out = (float*)d_out;

    dim3 grid(MM / TM, II / TN);   // (128, 64)
    gemm_fused_kernel<<<grid, 256>>>(x, Wa, ba, Wi, bi, gate);
    scan_kernel<<<(BB * II) / 128, 128>>>(out);
}

// round 3
// speedup vs baseline: 1.7347x; 1.7347x over previous
#include <cuda_runtime.h>
#include <cuda_fp16.h>
#include <cstdint>

// Problem dims (fixed per reference setup_inputs)
#define BB 8
#define SS 2048
#define DD 512
#define II 2048
#define MM (BB*SS)   // 16384 rows (b*S+s)

#define LN3 1.0986122886681098f

// GEMM tiling
#define CTA_M 128
#define CTA_N 64
#define TK 64
#define NCHUNK (DD/TK)       // 8
#define STAGES 4
#define STAGE_BYTES 32768    // x 16K + Wa 8K + Wi 8K
#define WA_OFF 16384
#define WI_OFF 24576

// Scratch
__device__ __half g_xh[(size_t)MM * DD];
__device__ __half g_wah[(size_t)II * DD];
__device__ __half g_wih[(size_t)II * DD];
__device__ float  g_a[(size_t)MM * II];   // TRANSPOSED [i, m]
__device__ float  g_c[(size_t)MM * II];

__device__ __forceinline__ uint32_t s2u(const void* p) {
    uint32_t a;
    asm("{ .reg .u64 t; cvta.to.shared.u64 t, %1; cvt.u32.u64 %0, t; }" : "=r"(a) : "l"(p));
    return a;
}

// SW128-style swizzle for 128-byte rows (64 halves)
__device__ __forceinline__ uint32_t swz(uint32_t o) { return o ^ ((o >> 3) & 0x70); }

__device__ __forceinline__ void cpa16(uint32_t dst, const void* src) {
    asm volatile("cp.async.cg.shared.global [%0], [%1], 16;" :: "r"(dst), "l"(src) : "memory");
}
__device__ __forceinline__ void cpa_commit() {
    asm volatile("cp.async.commit_group;" ::: "memory");
}
__device__ __forceinline__ void cpa_wait3() {
    asm volatile("cp.async.wait_group 3;" ::: "memory");
}

__device__ __forceinline__ void ldm_x4(uint32_t* r, uint32_t addr) {
    asm volatile("ldmatrix.sync.aligned.m8n8.x4.shared.b16 {%0,%1,%2,%3}, [%4];"
                 : "=r"(r[0]), "=r"(r[1]), "=r"(r[2]), "=r"(r[3]) : "r"(addr));
}

__device__ __forceinline__ void mma_f16(float* d, const uint32_t* a, uint32_t b0, uint32_t b1) {
    asm volatile(
        "mma.sync.aligned.m16n8k16.row.col.f32.f16.f16.f32 "
        "{%0,%1,%2,%3}, {%4,%5,%6,%7}, {%8,%9}, {%0,%1,%2,%3};\n"
        : "+f"(d[0]), "+f"(d[1]), "+f"(d[2]), "+f"(d[3])
        : "r"(a[0]), "r"(a[1]), "r"(a[2]), "r"(a[3]), "r"(b0), "r"(b1));
}

__device__ __forceinline__ float sigmoidf_(float v) {
    return 1.0f / (1.0f + __expf(-v));
}

// ---- fp32 -> fp16 convert (grid-stride over float4) ----
__global__ void cvt_kernel(const float4* __restrict__ src, __half2* __restrict__ dst, int n4)
{
    int i = blockIdx.x * blockDim.x + threadIdx.x;
    if (i < n4) {
        float4 v = src[i];
        dst[2 * i]     = __floats2half2_rn(v.x, v.y);
        dst[2 * i + 1] = __floats2half2_rn(v.z, v.w);
    }
}

// ---- GEMM: pa/pi = x @ {Wa,Wi}^T, fp16 mma, fused gate epilogue ----
// grid (MM/CTA_M, II/CTA_N) = (128, 32), 256 threads, dyn smem = 4 stages.
__global__ void __launch_bounds__(256) gemm_fused_kernel(
    const float* __restrict__ ba, const float* __restrict__ bi,
    const float* __restrict__ gate)
{
    extern __shared__ char smem[];
    const uint32_t sbase = s2u(smem);

    const int tid  = threadIdx.x;
    const int wid  = tid >> 5;
    const int lane = tid & 31;
    const int wm   = wid >> 1;          // 0..3 -> 32-row slice
    const int wn   = wid & 1;           // 0..1 -> 32-col slice
    const int g    = lane >> 2;         // 0..7
    const int tg   = lane & 3;          // 0..3
    const int m_blk = blockIdx.x * CTA_M;
    const int n_blk = blockIdx.y * CTA_N;

    float accA[2][4][4], accB[2][4][4];
    #pragma unroll
    for (int mt = 0; mt < 2; mt++)
        #pragma unroll
        for (int nt = 0; nt < 4; nt++)
            #pragma unroll
            for (int r = 0; r < 4; r++) { accA[mt][nt][r] = 0.f; accB[mt][nt][r] = 0.f; }

    // issue one chunk's cp.asyncs into a stage slot
    auto issue = [&](int kc, int slot) {
        const uint32_t sb = sbase + slot * STAGE_BYTES;
        const int k0 = kc * TK;
        #pragma unroll
        for (int t = 0; t < 4; t++) {                    // x: 128 rows x 128B
            int f = tid + t * 256; int r = f >> 3, c = f & 7;
            cpa16(sb + swz(r * 128 + c * 16),
                  g_xh + (size_t)(m_blk + r) * DD + k0 + c * 8);
        }
        #pragma unroll
        for (int t = 0; t < 2; t++) {                    // Wa, Wi: 64 rows x 128B each
            int f = tid + t * 256; int r = f >> 3, c = f & 7;
            cpa16(sb + WA_OFF + swz(r * 128 + c * 16),
                  g_wah + (size_t)(n_blk + r) * DD + k0 + c * 8);
            cpa16(sb + WI_OFF + swz(r * 128 + c * 16),
                  g_wih + (size_t)(n_blk + r) * DD + k0 + c * 8);
        }
        cpa_commit();
    };

    issue(0, 0); issue(1, 1); issue(2, 2);

    const int arow = lane & 15;          // ldmatrix row within 16
    const int acol = (lane >> 4) * 16;   // 16B half-select

    for (int kc = 0; kc < NCHUNK; kc++) {
        if (kc + 3 < NCHUNK) issue(kc + 3, (kc + 3) & 3);
        else cpa_commit();               // keep group counting uniform
        cpa_wait3();
        __syncthreads();

        const uint32_t sb = sbase + (kc & 3) * STAGE_BYTES;
        #pragma unroll
        for (int kk = 0; kk < 4; kk++) {
            const uint32_t kb = kk * 32 + acol;
            uint32_t a[2][4], bwa[2][4], bwi[2][4];
            #pragma unroll
            for (int mt = 0; mt < 2; mt++) {
                int row = wm * 32 + mt * 16 + arow;
                ldm_x4(a[mt], sb + swz(row * 128 + kb));
            }
            #pragma unroll
            for (int bt = 0; bt < 2; bt++) {
                int row = wn * 32 + bt * 16 + arow;
                ldm_x4(bwa[bt], sb + WA_OFF + swz(row * 128 + kb));
                ldm_x4(bwi[bt], sb + WI_OFF + swz(row * 128 + kb));
            }
            #pragma unroll
            for (int mt = 0; mt < 2; mt++)
                #pragma unroll
                for (int nt = 0; nt < 4; nt++) {
                    const int bt = nt >> 1, sub = nt & 1;
                    mma_f16(accA[mt][nt], a[mt], bwa[bt][sub], bwa[bt][sub + 2]);
                    mma_f16(accB[mt][nt], a[mt], bwi[bt][sub], bwi[bt][sub + 2]);
                }
        }
        __syncthreads();
    }

    // ---- fused epilogue -> adaptive_alpha, drive; TRANSPOSED [i,m] stores ----
    #pragma unroll
    for (int nt = 0; nt < 4; nt++) {
        const int i0 = n_blk + wn * 32 + nt * 8 + 2 * tg;
        const float ba0 = __ldg(&ba[i0]),   ba1 = __ldg(&ba[i0 + 1]);
        const float bi0 = __ldg(&bi[i0]),   bi1 = __ldg(&bi[i0 + 1]);
        const float al0 = sigmoidf_(__ldg(&gate[i0]));
        const float al1 = sigmoidf_(__ldg(&gate[i0 + 1]));
        #pragma unroll
        for (int mt = 0; mt < 2; mt++) {
            const int m0 = m_blk + wm * 32 + mt * 16 + g;
            #pragma unroll
            for (int r = 0; r < 4; r++) {
                const int m = m0 + (r >> 1) * 8;            // r0,r1 row g; r2,r3 row g+8
                const int i = i0 + (r & 1);
                const float bav = (r & 1) ? ba1 : ba0;
                const float biv = (r & 1) ? bi1 : bi0;
                const float alv = (r & 1) ? al1 : al0;
                float pa = accA[mt][nt][r] + bav;
                float pi = accB[mt][nt][r] + biv;
                float rg = sigmoidf_(pa);
                float ig = sigmoidf_(pi);
                float aa = alv * __expf(-LN3 * rg);
                float dr = sqrtf(fmaxf(1.0f - aa * aa, 0.0f)) * (ig * pi);
                g_a[(size_t)i * MM + m] = aa;
                g_c[(size_t)i * MM + m] = dr;
            }
        }
    }
}

// ---- Sequential scan per (b,i): contiguous float4 reads along s ----
__global__ void __launch_bounds__(64, 8) scan_kernel(float* __restrict__ out)
{
    const int idx = blockIdx.x * 64 + threadIdx.x;
    const int b = idx >> 11;
    const int i = idx & (II - 1);
    const float4* ap = reinterpret_cast<const float4*>(g_a + (size_t)i * MM + b * SS);
    const float4* cp = reinterpret_cast<const float4*>(g_c + (size_t)i * MM + b * SS);
    float* op = out + (size_t)b * SS * II + i;

    float4 A[4], C[4], A2[4], C2[4];
    #pragma unroll
    for (int j = 0; j < 4; j++) { A[j] = ap[j]; C[j] = cp[j]; }

    float h = 0.0f;
    for (int s0 = 0; s0 < SS; s0 += 16) {
        if (s0 + 16 < SS) {
            const int q = (s0 >> 2) + 4;
            #pragma unroll
            for (int j = 0; j < 4; j++) { A2[j] = ap[q + j]; C2[j] = cp[q + j]; }
        }
        #pragma unroll
        for (int j = 0; j < 4; j++) {
            h = fmaf(A[j].x, h, C[j].x); op[(size_t)(s0 + 4 * j + 0) * II] = h;
            h = fmaf(A[j].y, h, C[j].y); op[(size_t)(s0 + 4 * j + 1) * II] = h;
            h = fmaf(A[j].z, h, C[j].z); op[(size_t)(s0 + 4 * j + 2) * II] = h;
            h = fmaf(A[j].w, h, C[j].w); op[(size_t)(s0 + 4 * j + 3) * II] = h;
        }
        #pragma unroll
        for (int j = 0; j < 4; j++) { A[j] = A2[j]; C[j] = C2[j]; }
    }
}

extern "C" void kernel_launch(void* const* d_in, const int* in_sizes, int n_in,
                              void* d_out, int out_size)
{
    const float* x    = (const float*)d_in[0];
    const float* Wa   = (const float*)d_in[1];
    const float* ba   = (const float*)d_in[2];
    const float* Wi   = (const float*)d_in[3];
    const float* bi   = (const float*)d_in[4];
    const float* gate = (const float*)d_in[5];
    float* out = (float*)d_out;

    __half* xh;  cudaGetSymbolAddress((void**)&xh,  g_xh);
    __half* wah; cudaGetSymbolAddress((void**)&wah, g_wah);
    __half* wih; cudaGetSymbolAddress((void**)&wih, g_wih);

    const int nx4 = MM * DD / 4;   // 2,097,152
    const int nw4 = II * DD / 4;   //   262,144
    cvt_kernel<<<(nx4 + 255) / 256, 256>>>((const float4*)x,  (__half2*)xh,  nx4);
    cvt_kernel<<<(nw4 + 255) / 256, 256>>>((const float4*)Wa, (__half2*)wah, nw4);
    cvt_kernel<<<(nw4 + 255) / 256, 256>>>((const float4*)Wi, (__half2*)wih, nw4);

    cudaFuncSetAttribute(gemm_fused_kernel,
                         cudaFuncAttributeMaxDynamicSharedMemorySize,
                         STAGES * STAGE_BYTES);
    dim3 grid(MM / CTA_M, II / CTA_N);   // (128, 32)
    gemm_fused_kernel<<<grid, 256, STAGES * STAGE_BYTES>>>(ba, bi, gate);

    scan_kernel<<<(BB * II) / 64, 64>>>(out);
}

// round 4
// speedup vs baseline: 2.1454x; 1.2368x over previous
#include <cuda_runtime.h>
#include <cuda_fp16.h>
#include <cstdint>

// Problem dims (fixed per reference setup_inputs)
#define BB 8
#define SS 2048
#define DD 512
#define II 2048
#define MM (BB*SS)   // 16384 rows (b*S+s)

#define LN3 1.0986122886681098f

// GEMM tiling
#define CTA_M 128
#define CTA_N 128
#define TK 64
#define NCHUNK (DD/TK)       // 8
#define STAGES 3
#define STAGE_BYTES 49152    // x 16K + Wa 16K + Wi 16K
#define WA_OFF 16384
#define WI_OFF 32768

// Scratch
__device__ __half g_xh[(size_t)MM * DD];
__device__ __half g_wah[(size_t)II * DD];
__device__ __half g_wih[(size_t)II * DD];
__device__ float  g_a[(size_t)MM * II];   // TRANSPOSED [i, m]
__device__ float  g_c[(size_t)MM * II];

__device__ __forceinline__ uint32_t s2u(const void* p) {
    uint32_t a;
    asm("{ .reg .u64 t; cvta.to.shared.u64 t, %1; cvt.u32.u64 %0, t; }" : "=r"(a) : "l"(p));
    return a;
}

// SW128-style swizzle for 128-byte rows (64 halves)
__device__ __forceinline__ uint32_t swz(uint32_t o) { return o ^ ((o >> 3) & 0x70); }

__device__ __forceinline__ void cpa16(uint32_t dst, const void* src) {
    asm volatile("cp.async.cg.shared.global [%0], [%1], 16;" :: "r"(dst), "l"(src) : "memory");
}
__device__ __forceinline__ void cpa_commit() {
    asm volatile("cp.async.commit_group;" ::: "memory");
}
__device__ __forceinline__ void cpa_wait2() {
    asm volatile("cp.async.wait_group 2;" ::: "memory");
}

__device__ __forceinline__ void ldm_x4(uint32_t* r, uint32_t addr) {
    asm volatile("ldmatrix.sync.aligned.m8n8.x4.shared.b16 {%0,%1,%2,%3}, [%4];"
                 : "=r"(r[0]), "=r"(r[1]), "=r"(r[2]), "=r"(r[3]) : "r"(addr));
}

__device__ __forceinline__ void mma_f16(float* d, const uint32_t* a, uint32_t b0, uint32_t b1) {
    asm volatile(
        "mma.sync.aligned.m16n8k16.row.col.f32.f16.f16.f32 "
        "{%0,%1,%2,%3}, {%4,%5,%6,%7}, {%8,%9}, {%0,%1,%2,%3};\n"
        : "+f"(d[0]), "+f"(d[1]), "+f"(d[2]), "+f"(d[3])
        : "r"(a[0]), "r"(a[1]), "r"(a[2]), "r"(a[3]), "r"(b0), "r"(b1));
}

__device__ __forceinline__ float sigmoidf_(float v) {
    return 1.0f / (1.0f + __expf(-v));
}

// ---- fp32 -> fp16 convert ----
__global__ void cvt_kernel(const float4* __restrict__ src, __half2* __restrict__ dst, int n4)
{
    int i = blockIdx.x * blockDim.x + threadIdx.x;
    if (i < n4) {
        float4 v = src[i];
        dst[2 * i]     = __floats2half2_rn(v.x, v.y);
        dst[2 * i + 1] = __floats2half2_rn(v.z, v.w);
    }
}

// ---- GEMM: pa/pi = x @ {Wa,Wi}^T, fp16 mma, fused gate epilogue ----
// grid (MM/CTA_M, II/CTA_N) = (128, 16), 512 threads (16 warps, 4x4 warp grid).
__global__ void __launch_bounds__(512, 1) gemm_fused_kernel(
    const float* __restrict__ ba, const float* __restrict__ bi,
    const float* __restrict__ gate)
{
    extern __shared__ char smem[];
    const uint32_t sbase = s2u(smem);

    const int tid  = threadIdx.x;
    const int wid  = tid >> 5;
    const int lane = tid & 31;
    const int wm   = wid >> 2;          // 0..3 -> 32-row slice
    const int wn   = wid & 3;           // 0..3 -> 32-col slice
    const int g    = lane >> 2;         // 0..7
    const int tg   = lane & 3;          // 0..3
    const int m_blk = blockIdx.x * CTA_M;
    const int n_blk = blockIdx.y * CTA_N;

    float accA[2][4][4], accB[2][4][4];
    #pragma unroll
    for (int mt = 0; mt < 2; mt++)
        #pragma unroll
        for (int nt = 0; nt < 4; nt++)
            #pragma unroll
            for (int r = 0; r < 4; r++) { accA[mt][nt][r] = 0.f; accB[mt][nt][r] = 0.f; }

    // issue one chunk's cp.asyncs into a stage slot (6 per thread)
    auto issue = [&](int kc, int slot) {
        const uint32_t sb = sbase + slot * STAGE_BYTES;
        const int k0 = kc * TK;
        #pragma unroll
        for (int t = 0; t < 2; t++) {                    // x: 128 rows x 128B
            int f = tid + t * 512; int r = f >> 3, c = f & 7;
            cpa16(sb + swz(r * 128 + c * 16),
                  g_xh + (size_t)(m_blk + r) * DD + k0 + c * 8);
        }
        #pragma unroll
        for (int t = 0; t < 2; t++) {                    // Wa, Wi: 128 rows x 128B each
            int f = tid + t * 512; int r = f >> 3, c = f & 7;
            cpa16(sb + WA_OFF + swz(r * 128 + c * 16),
                  g_wah + (size_t)(n_blk + r) * DD + k0 + c * 8);
            cpa16(sb + WI_OFF + swz(r * 128 + c * 16),
                  g_wih + (size_t)(n_blk + r) * DD + k0 + c * 8);
        }
        cpa_commit();
    };

    issue(0, 0); issue(1, 1);

    // hoisted swizzle bases: swz(row*128 + kb) = row*128 + (kb ^ ((row&7)<<4))
    const int arow = lane & 15;
    const uint32_t acol = (lane >> 4) << 4;   // 0 or 16
    uint32_t abase[2], axor[2], bbase[2], bxor[2];
    #pragma unroll
    for (int mt = 0; mt < 2; mt++) {
        int row = wm * 32 + mt * 16 + arow;
        abase[mt] = row * 128; axor[mt] = (row & 7) << 4;
    }
    #pragma unroll
    for (int bt = 0; bt < 2; bt++) {
        int row = wn * 32 + bt * 16 + arow;
        bbase[bt] = row * 128; bxor[bt] = (row & 7) << 4;
    }

    for (int kc = 0; kc < NCHUNK; kc++) {
        if (kc + 2 < NCHUNK) issue(kc + 2, (kc + 2) % STAGES);
        else cpa_commit();               // keep group counting uniform
        cpa_wait2();
        __syncthreads();

        const uint32_t sb = sbase + (kc % STAGES) * STAGE_BYTES;
        #pragma unroll
        for (int kk = 0; kk < 4; kk++) {
            const uint32_t kb = kk * 32 + acol;
            uint32_t a[2][4], bwa[2][4], bwi[2][4];
            #pragma unroll
            for (int mt = 0; mt < 2; mt++)
                ldm_x4(a[mt], sb + abase[mt] + (kb ^ axor[mt]));
            #pragma unroll
            for (int bt = 0; bt < 2; bt++) {
                ldm_x4(bwa[bt], sb + WA_OFF + bbase[bt] + (kb ^ bxor[bt]));
                ldm_x4(bwi[bt], sb + WI_OFF + bbase[bt] + (kb ^ bxor[bt]));
            }
            #pragma unroll
            for (int mt = 0; mt < 2; mt++)
                #pragma unroll
                for (int nt = 0; nt < 4; nt++) {
                    const int bt = nt >> 1, sub = nt & 1;
                    mma_f16(accA[mt][nt], a[mt], bwa[bt][sub], bwa[bt][sub + 2]);
                    mma_f16(accB[mt][nt], a[mt], bwi[bt][sub], bwi[bt][sub + 2]);
                }
        }
        __syncthreads();
    }

    // ---- fused epilogue -> adaptive_alpha, drive; TRANSPOSED [i,m] stores ----
    #pragma unroll
    for (int nt = 0; nt < 4; nt++) {
        const int i0 = n_blk + wn * 32 + nt * 8 + 2 * tg;
        const float ba0 = __ldg(&ba[i0]),   ba1 = __ldg(&ba[i0 + 1]);
        const float bi0 = __ldg(&bi[i0]),   bi1 = __ldg(&bi[i0 + 1]);
        const float al0 = sigmoidf_(__ldg(&gate[i0]));
        const float al1 = sigmoidf_(__ldg(&gate[i0 + 1]));
        #pragma unroll
        for (int mt = 0; mt < 2; mt++) {
            const int m0 = m_blk + wm * 32 + mt * 16 + g;
            #pragma unroll
            for (int r = 0; r < 4; r++) {
                const int m = m0 + (r >> 1) * 8;
                const int i = i0 + (r & 1);
                const float bav = (r & 1) ? ba1 : ba0;
                const float biv = (r & 1) ? bi1 : bi0;
                const float alv = (r & 1) ? al1 : al0;
                float pa = accA[mt][nt][r] + bav;
                float pi = accB[mt][nt][r] + biv;
                float rg = sigmoidf_(pa);
                float ig = sigmoidf_(pi);
                float aa = alv * __expf(-LN3 * rg);
                float dr = sqrtf(fmaxf(1.0f - aa * aa, 0.0f)) * (ig * pi);
                g_a[(size_t)i * MM + m] = aa;
                g_c[(size_t)i * MM + m] = dr;
            }
        }
    }
}

// ---- Sequential scan per (b,i): contiguous float4 reads along s ----
__global__ void __launch_bounds__(64, 8) scan_kernel(float* __restrict__ out)
{
    const int idx = blockIdx.x * 64 + threadIdx.x;
    const int b = idx >> 11;
    const int i = idx & (II - 1);
    const float4* ap = reinterpret_cast<const float4*>(g_a + (size_t)i * MM + b * SS);
    const float4* cp = reinterpret_cast<const float4*>(g_c + (size_t)i * MM + b * SS);
    float* op = out + (size_t)b * SS * II + i;

    float4 A[4], C[4], A2[4], C2[4];
    #pragma unroll
    for (int j = 0; j < 4; j++) { A[j] = ap[j]; C[j] = cp[j]; }

    float h = 0.0f;
    for (int s0 = 0; s0 < SS; s0 += 16) {
        if (s0 + 16 < SS) {
            const int q = (s0 >> 2) + 4;
            #pragma unroll
            for (int j = 0; j < 4; j++) { A2[j] = ap[q + j]; C2[j] = cp[q + j]; }
        }
        #pragma unroll
        for (int j = 0; j < 4; j++) {
            h = fmaf(A[j].x, h, C[j].x); op[(size_t)(s0 + 4 * j + 0) * II] = h;
            h = fmaf(A[j].y, h, C[j].y); op[(size_t)(s0 + 4 * j + 1) * II] = h;
            h = fmaf(A[j].z, h, C[j].z); op[(size_t)(s0 + 4 * j + 2) * II] = h;
            h = fmaf(A[j].w, h, C[j].w); op[(size_t)(s0 + 4 * j + 3) * II] = h;
        }
        #pragma unroll
        for (int j = 0; j < 4; j++) { A[j] = A2[j]; C[j] = C2[j]; }
    }
}

extern "C" void kernel_launch(void* const* d_in, const int* in_sizes, int n_in,
                              void* d_out, int out_size)
{
    const float* x    = (const float*)d_in[0];
    const float* Wa   = (const float*)d_in[1];
    const float* ba   = (const float*)d_in[2];
    const float* Wi   = (const float*)d_in[3];
    const float* bi   = (const float*)d_in[4];
    const float* gate = (const float*)d_in[5];
    float* out = (float*)d_out;

    __half* xh;  cudaGetSymbolAddress((void**)&xh,  g_xh);
    __half* wah; cudaGetSymbolAddress((void**)&wah, g_wah);
    __half* wih; cudaGetSymbolAddress((void**)&wih, g_wih);

    const int nx4 = MM * DD / 4;
    const int nw4 = II * DD / 4;
    cvt_kernel<<<(nx4 + 255) / 256, 256>>>((const float4*)x,  (__half2*)xh,  nx4);
    cvt_kernel<<<(nw4 + 255) / 256, 256>>>((const float4*)Wa, (__half2*)wah, nw4);
    cvt_kernel<<<(nw4 + 255) / 256, 256>>>((const float4*)Wi, (__half2*)wih, nw4);

    cudaFuncSetAttribute(gemm_fused_kernel,
                         cudaFuncAttributeMaxDynamicSharedMemorySize,
                         STAGES * STAGE_BYTES);
    dim3 grid(MM / CTA_M, II / CTA_N);   // (128, 16)
    gemm_fused_kernel<<<grid, 512, STAGES * STAGE_BYTES>>>(ba, bi, gate);

    scan_kernel<<<(BB * II) / 64, 64>>>(out);
}

// round 5
// speedup vs baseline: 2.3215x; 1.0821x over previous
#include <cuda_runtime.h>
#include <cuda_fp16.h>
#include <cstdint>

// Problem dims (fixed per reference setup_inputs)
#define BB 8
#define SS 2048
#define DD 512
#define II 2048
#define MM (BB*SS)   // 16384 rows (b*S+s)

#define LN3 1.0986122886681098f

// GEMM tiling
#define CTA_M 128
#define CTA_N 128
#define TK 64
#define NCHUNK (DD/TK)       // 8
#define STAGES 3
#define STAGE_BYTES 49152    // x 16K + Wa 16K + Wi 16K
#define WA_OFF 16384
#define WI_OFF 32768

// Scratch
__device__ __half  g_xh[(size_t)MM * DD];
__device__ __half  g_wah[(size_t)II * DD];
__device__ __half  g_wih[(size_t)II * DD];
__device__ __half2 g_ac[(size_t)MM * II];   // TRANSPOSED [i, m], packed (alpha, drive)

__device__ __forceinline__ uint32_t s2u(const void* p) {
    uint32_t a;
    asm("{ .reg .u64 t; cvta.to.shared.u64 t, %1; cvt.u32.u64 %0, t; }" : "=r"(a) : "l"(p));
    return a;
}

// SW128-style swizzle for 128-byte rows (64 halves)
__device__ __forceinline__ uint32_t swz(uint32_t o) { return o ^ ((o >> 3) & 0x70); }

__device__ __forceinline__ void cpa16(uint32_t dst, const void* src) {
    asm volatile("cp.async.cg.shared.global [%0], [%1], 16;" :: "r"(dst), "l"(src) : "memory");
}
__device__ __forceinline__ void cpa_commit() {
    asm volatile("cp.async.commit_group;" ::: "memory");
}
__device__ __forceinline__ void cpa_wait2() {
    asm volatile("cp.async.wait_group 2;" ::: "memory");
}

__device__ __forceinline__ void ldm_x4(uint32_t* r, uint32_t addr) {
    asm volatile("ldmatrix.sync.aligned.m8n8.x4.shared.b16 {%0,%1,%2,%3}, [%4];"
                 : "=r"(r[0]), "=r"(r[1]), "=r"(r[2]), "=r"(r[3]) : "r"(addr));
}

__device__ __forceinline__ void mma_f16(float* d, const uint32_t* a, uint32_t b0, uint32_t b1) {
    asm volatile(
        "mma.sync.aligned.m16n8k16.row.col.f32.f16.f16.f32 "
        "{%0,%1,%2,%3}, {%4,%5,%6,%7}, {%8,%9}, {%0,%1,%2,%3};\n"
        : "+f"(d[0]), "+f"(d[1]), "+f"(d[2]), "+f"(d[3])
        : "r"(a[0]), "r"(a[1]), "r"(a[2]), "r"(a[3]), "r"(b0), "r"(b1));
}

__device__ __forceinline__ float sigmoidf_(float v) {
    return 1.0f / (1.0f + __expf(-v));
}

// ---- fp32 -> fp16 convert ----
__global__ void cvt_kernel(const float4* __restrict__ src, __half2* __restrict__ dst, int n4)
{
    int i = blockIdx.x * blockDim.x + threadIdx.x;
    if (i < n4) {
        float4 v = src[i];
        dst[2 * i]     = __floats2half2_rn(v.x, v.y);
        dst[2 * i + 1] = __floats2half2_rn(v.z, v.w);
    }
}

// ---- GEMM: pa/pi = x @ {Wa,Wi}^T, fp16 mma, fused gate epilogue ----
// grid (MM/CTA_M, II/CTA_N) = (128, 16), 512 threads (16 warps, 4x4 warp grid).
__global__ void __launch_bounds__(512, 1) gemm_fused_kernel(
    const float* __restrict__ ba, const float* __restrict__ bi,
    const float* __restrict__ gate)
{
    extern __shared__ char smem[];
    const uint32_t sbase = s2u(smem);

    const int tid  = threadIdx.x;
    const int wid  = tid >> 5;
    const int lane = tid & 31;
    const int wm   = wid >> 2;          // 0..3 -> 32-row slice
    const int wn   = wid & 3;           // 0..3 -> 32-col slice
    const int g    = lane >> 2;         // 0..7
    const int tg   = lane & 3;          // 0..3
    const int m_blk = blockIdx.x * CTA_M;
    const int n_blk = blockIdx.y * CTA_N;

    float accA[2][4][4], accB[2][4][4];
    #pragma unroll
    for (int mt = 0; mt < 2; mt++)
        #pragma unroll
        for (int nt = 0; nt < 4; nt++)
            #pragma unroll
            for (int r = 0; r < 4; r++) { accA[mt][nt][r] = 0.f; accB[mt][nt][r] = 0.f; }

    // issue one chunk's cp.asyncs into a stage slot (6 per thread)
    auto issue = [&](int kc, int slot) {
        const uint32_t sb = sbase + slot * STAGE_BYTES;
        const int k0 = kc * TK;
        #pragma unroll
        for (int t = 0; t < 2; t++) {                    // x: 128 rows x 128B
            int f = tid + t * 512; int r = f >> 3, c = f & 7;
            cpa16(sb + swz(r * 128 + c * 16),
                  g_xh + (size_t)(m_blk + r) * DD + k0 + c * 8);
        }
        #pragma unroll
        for (int t = 0; t < 2; t++) {                    // Wa, Wi: 128 rows x 128B each
            int f = tid + t * 512; int r = f >> 3, c = f & 7;
            cpa16(sb + WA_OFF + swz(r * 128 + c * 16),
                  g_wah + (size_t)(n_blk + r) * DD + k0 + c * 8);
            cpa16(sb + WI_OFF + swz(r * 128 + c * 16),
                  g_wih + (size_t)(n_blk + r) * DD + k0 + c * 8);
        }
        cpa_commit();
    };

    issue(0, 0); issue(1, 1);

    // Per-fragment swizzled offsets. swz(row*128 + kb) with kb = kk*32 + acol:
    //   = row*128 + ((acol ^ ((row&7)<<4)) ^ kk*32)   (kk bits never carry)
    const int arow = lane & 15;
    const uint32_t acol = (lane >> 4) << 4;   // 0 or 16
    uint32_t aoff[2], woff[2];
    #pragma unroll
    for (int mt = 0; mt < 2; mt++) {
        int row = wm * 32 + mt * 16 + arow;
        aoff[mt] = row * 128 + (acol ^ ((row & 7) << 4));
    }
    #pragma unroll
    for (int bt = 0; bt < 2; bt++) {
        int row = wn * 32 + bt * 16 + arow;
        woff[bt] = WA_OFF + row * 128 + (acol ^ ((row & 7) << 4));
    }

    for (int kc = 0; kc < NCHUNK; kc++) {
        if (kc + 2 < NCHUNK) issue(kc + 2, (kc + 2) % STAGES);
        else cpa_commit();               // keep group counting uniform
        cpa_wait2();
        __syncthreads();

        const uint32_t sb = sbase + (kc % STAGES) * STAGE_BYTES;
        uint32_t fa[2], fwa[2];
        fa[0] = sb + aoff[0];  fa[1] = sb + aoff[1];
        fwa[0] = sb + woff[0]; fwa[1] = sb + woff[1];

        #pragma unroll
        for (int kk = 0; kk < 4; kk++) {
            const uint32_t kx = kk * 32;
            uint32_t a[2][4], bwa[2][4], bwi[2][4];
            #pragma unroll
            for (int mt = 0; mt < 2; mt++)
                ldm_x4(a[mt], fa[mt] ^ kx);
            #pragma unroll
            for (int bt = 0; bt < 2; bt++) {
                ldm_x4(bwa[bt], fwa[bt] ^ kx);
                ldm_x4(bwi[bt], (fwa[bt] + (WI_OFF - WA_OFF)) ^ kx);
            }
            #pragma unroll
            for (int mt = 0; mt < 2; mt++)
                #pragma unroll
                for (int nt = 0; nt < 4; nt++) {
                    const int bt = nt >> 1, sub = nt & 1;
                    mma_f16(accA[mt][nt], a[mt], bwa[bt][sub], bwa[bt][sub + 2]);
                    mma_f16(accB[mt][nt], a[mt], bwi[bt][sub], bwi[bt][sub + 2]);
                }
        }
        __syncthreads();
    }

    // ---- fused epilogue -> packed half2(alpha, drive), TRANSPOSED [i,m] ----
    #pragma unroll
    for (int nt = 0; nt < 4; nt++) {
        const int i0 = n_blk + wn * 32 + nt * 8 + 2 * tg;
        const float ba0 = __ldg(&ba[i0]),   ba1 = __ldg(&ba[i0 + 1]);
        const float bi0 = __ldg(&bi[i0]),   bi1 = __ldg(&bi[i0 + 1]);
        const float al0 = sigmoidf_(__ldg(&gate[i0]));
        const float al1 = sigmoidf_(__ldg(&gate[i0 + 1]));
        #pragma unroll
        for (int mt = 0; mt < 2; mt++) {
            const int m0 = m_blk + wm * 32 + mt * 16 + g;
            #pragma unroll
            for (int r = 0; r < 4; r++) {
                const int m = m0 + (r >> 1) * 8;
                const int i = i0 + (r & 1);
                const float bav = (r & 1) ? ba1 : ba0;
                const float biv = (r & 1) ? bi1 : bi0;
                const float alv = (r & 1) ? al1 : al0;
                float pa = accA[mt][nt][r] + bav;
                float pi = accB[mt][nt][r] + biv;
                float rg = sigmoidf_(pa);
                float ig = sigmoidf_(pi);
                float aa = alv * __expf(-LN3 * rg);
                float dr = sqrtf(fmaxf(1.0f - aa * aa, 0.0f)) * (ig * pi);
                g_ac[(size_t)i * MM + m] = __floats2half2_rn(aa, dr);
            }
        }
    }
}

// ---- Sequential scan per (b,i): contiguous uint4 reads of packed (a,c) ----
// 32 s-steps per iter = 8 uint4 (128B) prefetched -> ~2MB chip-wide in flight.
__global__ void __launch_bounds__(64, 8) scan_kernel(float* __restrict__ out)
{
    const int idx = blockIdx.x * 64 + threadIdx.x;
    const int b = idx >> 11;
    const int i = idx & (II - 1);
    const uint4* acp = reinterpret_cast<const uint4*>(g_ac + (size_t)i * MM + b * SS);
    float* op = out + (size_t)b * SS * II + i;

    uint4 U[8], P[8];
    #pragma unroll
    for (int j = 0; j < 8; j++) U[j] = acp[j];

    float h = 0.0f;
    for (int s0 = 0; s0 < SS; s0 += 32) {
        if (s0 + 32 < SS) {
            const int q = (s0 >> 2) + 8;
            #pragma unroll
            for (int j = 0; j < 8; j++) P[j] = acp[q + j];
        }
        #pragma unroll
        for (int j = 0; j < 8; j++) {
            const uint32_t w[4] = { U[j].x, U[j].y, U[j].z, U[j].w };
            #pragma unroll
            for (int k = 0; k < 4; k++) {
                float2 p = __half22float2(*reinterpret_cast<const __half2*>(&w[k]));
                h = fmaf(p.x, h, p.y);
                op[(size_t)(s0 + j * 4 + k) * II] = h;
            }
        }
        #pragma unroll
        for (int j = 0; j < 8; j++) U[j] = P[j];
    }
}

extern "C" void kernel_launch(void* const* d_in, const int* in_sizes, int n_in,
                              void* d_out, int out_size)
{
    const float* x    = (const float*)d_in[0];
    const float* Wa   = (const float*)d_in[1];
    const float* ba   = (const float*)d_in[2];
    const float* Wi   = (const float*)d_in[3];
    const float* bi   = (const float*)d_in[4];
    const float* gate = (const float*)d_in[5];
    float* out = (float*)d_out;

    __half* xh;  cudaGetSymbolAddress((void**)&xh,  g_xh);
    __half* wah; cudaGetSymbolAddress((void**)&wah, g_wah);
    __half* wih; cudaGetSymbolAddress((void**)&wih, g_wih);

    const int nx4 = MM * DD / 4;
    const int nw4 = II * DD / 4;
    cvt_kernel<<<(nx4 + 255) / 256, 256>>>((const float4*)x,  (__half2*)xh,  nx4);
    cvt_kernel<<<(nw4 + 255) / 256, 256>>>((const float4*)Wa, (__half2*)wah, nw4);
    cvt_kernel<<<(nw4 + 255) / 256, 256>>>((const float4*)Wi, (__half2*)wih, nw4);

    cudaFuncSetAttribute(gemm_fused_kernel,
                         cudaFuncAttributeMaxDynamicSharedMemorySize,
                         STAGES * STAGE_BYTES);
    dim3 grid(MM / CTA_M, II / CTA_N);   // (128, 16)
    gemm_fused_kernel<<<grid, 512, STAGES * STAGE_BYTES>>>(ba, bi, gate);

    scan_kernel<<<(BB * II) / 64, 64>>>(out);
}

// round 6
// speedup vs baseline: 2.3607x; 1.0169x over previous
#include <cuda_runtime.h>
#include <cuda_fp16.h>
#include <cstdint>

// Problem dims (fixed per reference setup_inputs)
#define BB 8
#define SS 2048
#define DD 512
#define II 2048
#define MM (BB*SS)   // 16384 rows (b*S+s)

#define LN3 1.0986122886681098f

// GEMM tiling
#define CTA_M 128
#define CTA_N 128
#define TK 64
#define NCHUNK (DD/TK)       // 8
#define STAGES 3
#define STAGE_BYTES 49152    // x 16K + Wa 16K + Wi 16K
#define WA_OFF 16384
#define WI_OFF 32768

// Scratch
__device__ __half  g_xh[(size_t)MM * DD];
__device__ __half  g_wah[(size_t)II * DD];
__device__ __half  g_wih[(size_t)II * DD];
__device__ __half2 g_ac[(size_t)MM * II];   // TRANSPOSED [i, m], packed (alpha, drive)

__device__ __forceinline__ uint32_t s2u(const void* p) {
    uint32_t a;
    asm("{ .reg .u64 t; cvta.to.shared.u64 t, %1; cvt.u32.u64 %0, t; }" : "=r"(a) : "l"(p));
    return a;
}

// SW128-style swizzle for 128-byte rows (64 halves)
__device__ __forceinline__ uint32_t swz(uint32_t o) { return o ^ ((o >> 3) & 0x70); }

__device__ __forceinline__ void cpa16(uint32_t dst, const void* src) {
    asm volatile("cp.async.cg.shared.global [%0], [%1], 16;" :: "r"(dst), "l"(src) : "memory");
}
__device__ __forceinline__ void cpa_commit() {
    asm volatile("cp.async.commit_group;" ::: "memory");
}
__device__ __forceinline__ void cpa_wait1() {
    asm volatile("cp.async.wait_group 1;" ::: "memory");
}

__device__ __forceinline__ void ldm_x4(uint32_t* r, uint32_t addr) {
    asm volatile("ldmatrix.sync.aligned.m8n8.x4.shared.b16 {%0,%1,%2,%3}, [%4];"
                 : "=r"(r[0]), "=r"(r[1]), "=r"(r[2]), "=r"(r[3]) : "r"(addr));
}

__device__ __forceinline__ void mma_f16(float* d, const uint32_t* a, uint32_t b0, uint32_t b1) {
    asm volatile(
        "mma.sync.aligned.m16n8k16.row.col.f32.f16.f16.f32 "
        "{%0,%1,%2,%3}, {%4,%5,%6,%7}, {%8,%9}, {%0,%1,%2,%3};\n"
        : "+f"(d[0]), "+f"(d[1]), "+f"(d[2]), "+f"(d[3])
        : "r"(a[0]), "r"(a[1]), "r"(a[2]), "r"(a[3]), "r"(b0), "r"(b1));
}

__device__ __forceinline__ float sigmoidf_(float v) {
    return 1.0f / (1.0f + __expf(-v));
}

// ---- fp32 -> fp16 convert ----
__global__ void cvt_kernel(const float4* __restrict__ src, __half2* __restrict__ dst, int n4)
{
    int i = blockIdx.x * blockDim.x + threadIdx.x;
    if (i < n4) {
        float4 v = src[i];
        dst[2 * i]     = __floats2half2_rn(v.x, v.y);
        dst[2 * i + 1] = __floats2half2_rn(v.z, v.w);
    }
}

// ---- GEMM: pa/pi = x @ {Wa,Wi}^T, fp16 mma, fused gate epilogue ----
// grid (MM/CTA_M, II/CTA_N) = (128, 16), 512 threads (16 warps, 4x4 warp grid).
__global__ void __launch_bounds__(512, 1) gemm_fused_kernel(
    const float* __restrict__ ba, const float* __restrict__ bi,
    const float* __restrict__ gate)
{
    extern __shared__ char smem[];
    const uint32_t sbase = s2u(smem);

    const int tid  = threadIdx.x;
    const int wid  = tid >> 5;
    const int lane = tid & 31;
    const int wm   = wid >> 2;          // 0..3 -> 32-row slice
    const int wn   = wid & 3;           // 0..3 -> 32-col slice
    const int g    = lane >> 2;         // 0..7
    const int tg   = lane & 3;          // 0..3
    const int m_blk = blockIdx.x * CTA_M;
    const int n_blk = blockIdx.y * CTA_N;

    float accA[2][4][4], accB[2][4][4];
    #pragma unroll
    for (int mt = 0; mt < 2; mt++)
        #pragma unroll
        for (int nt = 0; nt < 4; nt++)
            #pragma unroll
            for (int r = 0; r < 4; r++) { accA[mt][nt][r] = 0.f; accB[mt][nt][r] = 0.f; }

    // issue one chunk's cp.asyncs into a stage slot (6 per thread)
    auto issue = [&](int kc, int slot) {
        const uint32_t sb = sbase + slot * STAGE_BYTES;
        const int k0 = kc * TK;
        #pragma unroll
        for (int t = 0; t < 2; t++) {                    // x: 128 rows x 128B
            int f = tid + t * 512; int r = f >> 3, c = f & 7;
            cpa16(sb + swz(r * 128 + c * 16),
                  g_xh + (size_t)(m_blk + r) * DD + k0 + c * 8);
        }
        #pragma unroll
        for (int t = 0; t < 2; t++) {                    // Wa, Wi: 128 rows x 128B each
            int f = tid + t * 512; int r = f >> 3, c = f & 7;
            cpa16(sb + WA_OFF + swz(r * 128 + c * 16),
                  g_wah + (size_t)(n_blk + r) * DD + k0 + c * 8);
            cpa16(sb + WI_OFF + swz(r * 128 + c * 16),
                  g_wih + (size_t)(n_blk + r) * DD + k0 + c * 8);
        }
        cpa_commit();
    };

    issue(0, 0); issue(1, 1);

    // Per-fragment swizzled offsets. swz(row*128 + kb) with kb = kk*32 + acol:
    //   = row*128 + ((acol ^ ((row&7)<<4)) ^ kk*32)   (kk bits never carry)
    const int arow = lane & 15;
    const uint32_t acol = (lane >> 4) << 4;   // 0 or 16
    uint32_t aoff[2], woff[2];
    #pragma unroll
    for (int mt = 0; mt < 2; mt++) {
        int row = wm * 32 + mt * 16 + arow;
        aoff[mt] = row * 128 + (acol ^ ((row & 7) << 4));
    }
    #pragma unroll
    for (int bt = 0; bt < 2; bt++) {
        int row = wn * 32 + bt * 16 + arow;
        woff[bt] = WA_OFF + row * 128 + (acol ^ ((row & 7) << 4));
    }

    for (int kc = 0; kc < NCHUNK; kc++) {
        cpa_wait1();            // group kc complete (kc+1 may still be in flight)
        __syncthreads();        // all warps' stage-kc data visible; prior stage reads done
        if (kc + 2 < NCHUNK) issue(kc + 2, (kc + 2) % STAGES);
        else cpa_commit();      // keep group counting uniform

        const uint32_t sb = sbase + (kc % STAGES) * STAGE_BYTES;
        uint32_t fa[2], fwa[2];
        fa[0] = sb + aoff[0];  fa[1] = sb + aoff[1];
        fwa[0] = sb + woff[0]; fwa[1] = sb + woff[1];

        // register double-buffered fragments: [buf][...]
        uint32_t a[2][2][4], bwa[2][2][4], bwi[2][2][4];

        // preload kk = 0 into buf 0
        #pragma unroll
        for (int mt = 0; mt < 2; mt++) ldm_x4(a[0][mt], fa[mt]);
        #pragma unroll
        for (int bt = 0; bt < 2; bt++) {
            ldm_x4(bwa[0][bt], fwa[bt]);
            ldm_x4(bwi[0][bt], (fwa[bt] + (WI_OFF - WA_OFF)));
        }

        #pragma unroll
        for (int kk = 0; kk < 4; kk++) {
            const int cur = kk & 1, nxt = cur ^ 1;
            if (kk < 3) {
                const uint32_t kx = (kk + 1) * 32;
                #pragma unroll
                for (int mt = 0; mt < 2; mt++) ldm_x4(a[nxt][mt], fa[mt] ^ kx);
                #pragma unroll
                for (int bt = 0; bt < 2; bt++) {
                    ldm_x4(bwa[nxt][bt], fwa[bt] ^ kx);
                    ldm_x4(bwi[nxt][bt], (fwa[bt] + (WI_OFF - WA_OFF)) ^ kx);
                }
            }
            #pragma unroll
            for (int mt = 0; mt < 2; mt++)
                #pragma unroll
                for (int nt = 0; nt < 4; nt++) {
                    const int bt = nt >> 1, sub = nt & 1;
                    mma_f16(accA[mt][nt], a[cur][mt], bwa[cur][bt][sub], bwa[cur][bt][sub + 2]);
                    mma_f16(accB[mt][nt], a[cur][mt], bwi[cur][bt][sub], bwi[cur][bt][sub + 2]);
                }
        }
    }

    // ---- fused epilogue -> packed half2(alpha, drive), TRANSPOSED [i,m] ----
    #pragma unroll
    for (int nt = 0; nt < 4; nt++) {
        const int i0 = n_blk + wn * 32 + nt * 8 + 2 * tg;
        const float ba0 = __ldg(&ba[i0]),   ba1 = __ldg(&ba[i0 + 1]);
        const float bi0 = __ldg(&bi[i0]),   bi1 = __ldg(&bi[i0 + 1]);
        const float al0 = sigmoidf_(__ldg(&gate[i0]));
        const float al1 = sigmoidf_(__ldg(&gate[i0 + 1]));
        #pragma unroll
        for (int mt = 0; mt < 2; mt++) {
            const int m0 = m_blk + wm * 32 + mt * 16 + g;
            #pragma unroll
            for (int r = 0; r < 4; r++) {
                const int m = m0 + (r >> 1) * 8;
                const int i = i0 + (r & 1);
                const float bav = (r & 1) ? ba1 : ba0;
                const float biv = (r & 1) ? bi1 : bi0;
                const float alv = (r & 1) ? al1 : al0;
                float pa = accA[mt][nt][r] + bav;
                float pi = accB[mt][nt][r] + biv;
                float rg = sigmoidf_(pa);
                float ig = sigmoidf_(pi);
                float aa = alv * __expf(-LN3 * rg);
                float dr = sqrtf(fmaxf(1.0f - aa * aa, 0.0f)) * (ig * pi);
                g_ac[(size_t)i * MM + m] = __floats2half2_rn(aa, dr);
            }
        }
    }
}

// ---- Sequential scan per (b,i): contiguous uint4 reads of packed (a,c) ----
// 32 s-steps per iter = 8 uint4 (128B) prefetched; 512 CTAs x 32 threads for
// fine-grained per-SM balance (~3.5 CTAs/SM).
__global__ void __launch_bounds__(32, 16) scan_kernel(float* __restrict__ out)
{
    const int idx = blockIdx.x * 32 + threadIdx.x;
    const int b = idx >> 11;
    const int i = idx & (II - 1);
    const uint4* acp = reinterpret_cast<const uint4*>(g_ac + (size_t)i * MM + b * SS);
    float* op = out + (size_t)b * SS * II + i;

    uint4 U[8], P[8];
    #pragma unroll
    for (int j = 0; j < 8; j++) U[j] = acp[j];

    float h = 0.0f;
    for (int s0 = 0; s0 < SS; s0 += 32) {
        if (s0 + 32 < SS) {
            const int q = (s0 >> 2) + 8;
            #pragma unroll
            for (int j = 0; j < 8; j++) P[j] = acp[q + j];
        }
        #pragma unroll
        for (int j = 0; j < 8; j++) {
            const uint32_t w[4] = { U[j].x, U[j].y, U[j].z, U[j].w };
            #pragma unroll
            for (int k = 0; k < 4; k++) {
                float2 p = __half22float2(*reinterpret_cast<const __half2*>(&w[k]));
                h = fmaf(p.x, h, p.y);
                op[(size_t)(s0 + j * 4 + k) * II] = h;
            }
        }
        #pragma unroll
        for (int j = 0; j < 8; j++) U[j] = P[j];
    }
}

extern "C" void kernel_launch(void* const* d_in, const int* in_sizes, int n_in,
                              void* d_out, int out_size)
{
    const float* x    = (const float*)d_in[0];
    const float* Wa   = (const float*)d_in[1];
    const float* ba   = (const float*)d_in[2];
    const float* Wi   = (const float*)d_in[3];
    const float* bi   = (const float*)d_in[4];
    const float* gate = (const float*)d_in[5];
    float* out = (float*)d_out;

    __half* xh;  cudaGetSymbolAddress((void**)&xh,  g_xh);
    __half* wah; cudaGetSymbolAddress((void**)&wah, g_wah);
    __half* wih; cudaGetSymbolAddress((void**)&wih, g_wih);

    const int nx4 = MM * DD / 4;
    const int nw4 = II * DD / 4;
    cvt_kernel<<<(nx4 + 255) / 256, 256>>>((const float4*)x,  (__half2*)xh,  nx4);
    cvt_kernel<<<(nw4 + 255) / 256, 256>>>((const float4*)Wa, (__half2*)wah, nw4);
    cvt_kernel<<<(nw4 + 255) / 256, 256>>>((const float4*)Wi, (__half2*)wih, nw4);

    cudaFuncSetAttribute(gemm_fused_kernel,
                         cudaFuncAttributeMaxDynamicSharedMemorySize,
                         STAGES * STAGE_BYTES);
    dim3 grid(MM / CTA_M, II / CTA_N);   // (128, 16)
    gemm_fused_kernel<<<grid, 512, STAGES * STAGE_BYTES>>>(ba, bi, gate);

    scan_kernel<<<(BB * II) / 32, 32>>>(out);
}

// round 7
// speedup vs baseline: 2.7857x; 1.1800x over previous
#include <cuda_runtime.h>
#include <cuda_fp16.h>
#include <cstdint>

// Problem dims (fixed per reference setup_inputs)
#define BB 8
#define SS 2048
#define DD 512
#define II 2048
#define MM (BB*SS)   // 16384 rows (b*S+s)
#define NN (2*II)    // 4096 interleaved output cols (even=pa, odd=pi)

#define LN3 1.0986122886681098f

// GEMM tiling
#define CTA_M 128
#define CTA_N 128          // = 64 channels
#define TK 64              // K halves per chunk (128B rows)
#define NCHUNK (DD/TK)     // 8
#define STAGES 3
#define STAGE_BYTES 32768  // x 16K + Wcat 16K
#define W_OFF 16384

// Scratch
__device__ __half  g_xh[(size_t)MM * DD];    // [m, k]
__device__ __half  g_wc[(size_t)NN * DD];    // interleaved [2i+p, k]
__device__ __half2 g_ac[(size_t)MM * II];    // TRANSPOSED [i, m], packed (alpha, drive)

__device__ __forceinline__ uint32_t s2u(const void* p) {
    uint32_t a;
    asm("{ .reg .u64 t; cvta.to.shared.u64 t, %1; cvt.u32.u64 %0, t; }" : "=r"(a) : "l"(p));
    return a;
}

// SW128-style swizzle for 128-byte rows (64 halves)
__device__ __forceinline__ uint32_t swz(uint32_t o) { return o ^ ((o >> 3) & 0x70); }

__device__ __forceinline__ void cpa16(uint32_t dst, const void* src) {
    asm volatile("cp.async.cg.shared.global [%0], [%1], 16;" :: "r"(dst), "l"(src) : "memory");
}
__device__ __forceinline__ void cpa_commit() {
    asm volatile("cp.async.commit_group;" ::: "memory");
}
__device__ __forceinline__ void cpa_wait1() {
    asm volatile("cp.async.wait_group 1;" ::: "memory");
}

__device__ __forceinline__ void ldm_x4(uint32_t* r, uint32_t addr) {
    asm volatile("ldmatrix.sync.aligned.m8n8.x4.shared.b16 {%0,%1,%2,%3}, [%4];"
                 : "=r"(r[0]), "=r"(r[1]), "=r"(r[2]), "=r"(r[3]) : "r"(addr));
}

__device__ __forceinline__ void mma_f16(float* d, const uint32_t* a, uint32_t b0, uint32_t b1) {
    asm volatile(
        "mma.sync.aligned.m16n8k16.row.col.f32.f16.f16.f32 "
        "{%0,%1,%2,%3}, {%4,%5,%6,%7}, {%8,%9}, {%0,%1,%2,%3};\n"
        : "+f"(d[0]), "+f"(d[1]), "+f"(d[2]), "+f"(d[3])
        : "r"(a[0]), "r"(a[1]), "r"(a[2]), "r"(a[3]), "r"(b0), "r"(b1));
}

__device__ __forceinline__ float sigmoidf_(float v) {
    return 1.0f / (1.0f + __expf(-v));
}

// ---- fp32 -> fp16 convert (x) ----
__global__ void cvt_kernel(const float4* __restrict__ src, __half2* __restrict__ dst, int n4)
{
    int i = blockIdx.x * blockDim.x + threadIdx.x;
    if (i < n4) {
        float4 v = src[i];
        dst[2 * i]     = __floats2half2_rn(v.x, v.y);
        dst[2 * i + 1] = __floats2half2_rn(v.z, v.w);
    }
}

// ---- fp32 -> fp16, interleaving W rows: dst row = 2*srcrow + parity ----
__global__ void cvt_w_kernel(const float4* __restrict__ src, int parity, int n4)
{
    int i = blockIdx.x * blockDim.x + threadIdx.x;
    if (i < n4) {
        float4 v = src[i];
        int row = i >> 7;              // DD/4 = 128 float4 per row
        int c4  = i & 127;
        __half2* dst = reinterpret_cast<__half2*>(g_wc) +
                       ((size_t)(2 * row + parity) * (DD / 2) + c4 * 2);
        dst[0] = __floats2half2_rn(v.x, v.y);
        dst[1] = __floats2half2_rn(v.z, v.w);
    }
}

// ---- GEMM: P = x @ Wcat^T (N=4096, interleaved), fused gate epilogue ----
// grid (MM/CTA_M, NN/CTA_N) = (128, 32), 256 threads (8 warps, 2x4), 2 CTAs/SM.
__global__ void __launch_bounds__(256, 2) gemm_fused_kernel(
    const float* __restrict__ ba, const float* __restrict__ bi,
    const float* __restrict__ gate)
{
    extern __shared__ char smem[];
    const uint32_t sbase = s2u(smem);

    const int tid  = threadIdx.x;
    const int wid  = tid >> 5;
    const int lane = tid & 31;
    const int wm   = wid >> 2;          // 0..1 -> 64-row slice
    const int wn   = wid & 3;           // 0..3 -> 32-col slice
    const int g    = lane >> 2;         // 0..7
    const int tg   = lane & 3;          // 0..3
    const int m_blk = blockIdx.x * CTA_M;
    const int n_blk = blockIdx.y * CTA_N;

    float acc[4][4][4];                 // [mt][nt][frag]
    #pragma unroll
    for (int mt = 0; mt < 4; mt++)
        #pragma unroll
        for (int nt = 0; nt < 4; nt++)
            #pragma unroll
            for (int r = 0; r < 4; r++) acc[mt][nt][r] = 0.f;

    // issue one chunk's cp.asyncs (8 per thread: 4 x-tile + 4 W-tile)
    auto issue = [&](int kc, int slot) {
        const uint32_t sb = sbase + slot * STAGE_BYTES;
        const int k0 = kc * TK;
        #pragma unroll
        for (int t = 0; t < 4; t++) {                    // x: 128 rows x 128B
            int f = tid + t * 256; int r = f >> 3, c = f & 7;
            cpa16(sb + swz(r * 128 + c * 16),
                  g_xh + (size_t)(m_blk + r) * DD + k0 + c * 8);
        }
        #pragma unroll
        for (int t = 0; t < 4; t++) {                    // Wcat: 128 rows x 128B
            int f = tid + t * 256; int r = f >> 3, c = f & 7;
            cpa16(sb + W_OFF + swz(r * 128 + c * 16),
                  g_wc + (size_t)(n_blk + r) * DD + k0 + c * 8);
        }
        cpa_commit();
    };

    issue(0, 0); issue(1, 1);

    // Per-fragment swizzled offsets. swz(row*128 + kb), kb = kk*32 + acol:
    //   = row*128 + ((acol ^ ((row&7)<<4)) ^ kk*32)   (kk bits never carry)
    const int arow = lane & 15;
    const uint32_t acol = (lane >> 4) << 4;   // 0 or 16
    uint32_t aoff[4], boff[2];
    #pragma unroll
    for (int mt = 0; mt < 4; mt++) {
        int row = wm * 64 + mt * 16 + arow;
        aoff[mt] = row * 128 + (acol ^ ((row & 7) << 4));
    }
    #pragma unroll
    for (int bt = 0; bt < 2; bt++) {
        int row = wn * 32 + bt * 16 + arow;
        boff[bt] = W_OFF + row * 128 + (acol ^ ((row & 7) << 4));
    }

    for (int kc = 0; kc < NCHUNK; kc++) {
        cpa_wait1();            // group kc complete
        __syncthreads();        // stage-kc visible; prior stage reads done
        if (kc + 2 < NCHUNK) issue(kc + 2, (kc + 2) % STAGES);
        else cpa_commit();      // keep group counting uniform

        const uint32_t sb = sbase + (kc % STAGES) * STAGE_BYTES;
        #pragma unroll
        for (int kk = 0; kk < 4; kk++) {
            const uint32_t kx = kk * 32;
            uint32_t a[4][4], bw[2][4];
            #pragma unroll
            for (int mt = 0; mt < 4; mt++) ldm_x4(a[mt], (sb + aoff[mt]) ^ kx);
            #pragma unroll
            for (int bt = 0; bt < 2; bt++) ldm_x4(bw[bt], (sb + boff[bt]) ^ kx);
            #pragma unroll
            for (int mt = 0; mt < 4; mt++)
                #pragma unroll
                for (int nt = 0; nt < 4; nt++) {
                    const int bt = nt >> 1, sub = nt & 1;
                    mma_f16(acc[mt][nt], a[mt], bw[bt][sub], bw[bt][sub + 2]);
                }
        }
    }

    // ---- fused epilogue: (c0,c1)=(pa,pi) of one channel -> half2(alpha,drive) ----
    #pragma unroll
    for (int nt = 0; nt < 4; nt++) {
        const int i = (n_blk >> 1) + wn * 16 + nt * 4 + tg;   // channel index
        const float bav = __ldg(&ba[i]);
        const float biv = __ldg(&bi[i]);
        const float alv = sigmoidf_(__ldg(&gate[i]));
        #pragma unroll
        for (int mt = 0; mt < 4; mt++) {
            const int m0 = m_blk + wm * 64 + mt * 16 + g;
            #pragma unroll
            for (int half = 0; half < 2; half++) {            // rows g, g+8
                const int m = m0 + half * 8;
                float pa = acc[mt][nt][2 * half]     + bav;
                float pi = acc[mt][nt][2 * half + 1] + biv;
                float rg = sigmoidf_(pa);
                float ig = sigmoidf_(pi);
                float aa = alv * __expf(-LN3 * rg);
                float dr = sqrtf(fmaxf(1.0f - aa * aa, 0.0f)) * (ig * pi);
                g_ac[(size_t)i * MM + m] = __floats2half2_rn(aa, dr);
            }
        }
    }
}

// ---- Sequential scan per (b,i): contiguous uint4 reads of packed (a,c) ----
// 64 s-steps per iter = 16 uint4 (256B) prefetched -> ~4MB chip-wide in flight.
__global__ void __launch_bounds__(32) scan_kernel(float* __restrict__ out)
{
    const int idx = blockIdx.x * 32 + threadIdx.x;
    const int b = idx >> 11;
    const int i = idx & (II - 1);
    const uint4* acp = reinterpret_cast<const uint4*>(g_ac + (size_t)i * MM + b * SS);
    float* op = out + (size_t)b * SS * II + i;

    uint4 U[16], P[16];
    #pragma unroll
    for (int j = 0; j < 16; j++) U[j] = acp[j];

    float h = 0.0f;
    for (int s0 = 0; s0 < SS; s0 += 64) {
        if (s0 + 64 < SS) {
            const int q = (s0 >> 2) + 16;
            #pragma unroll
            for (int j = 0; j < 16; j++) P[j] = acp[q + j];
        }
        #pragma unroll
        for (int j = 0; j < 16; j++) {
            const uint32_t w[4] = { U[j].x, U[j].y, U[j].z, U[j].w };
            #pragma unroll
            for (int k = 0; k < 4; k++) {
                float2 p = __half22float2(*reinterpret_cast<const __half2*>(&w[k]));
                h = fmaf(p.x, h, p.y);
                op[(size_t)(s0 + j * 4 + k) * II] = h;
            }
        }
        #pragma unroll
        for (int j = 0; j < 16; j++) U[j] = P[j];
    }
}

extern "C" void kernel_launch(void* const* d_in, const int* in_sizes, int n_in,
                              void* d_out, int out_size)
{
    const float* x    = (const float*)d_in[0];
    const float* Wa   = (const float*)d_in[1];
    const float* ba   = (const float*)d_in[2];
    const float* Wi   = (const float*)d_in[3];
    const float* bi   = (const float*)d_in[4];
    const float* gate = (const float*)d_in[5];
    float* out = (float*)d_out;

    __half* xh; cudaGetSymbolAddress((void**)&xh, g_xh);

    const int nx4 = MM * DD / 4;
    const int nw4 = II * DD / 4;
    cvt_kernel<<<(nx4 + 255) / 256, 256>>>((const float4*)x, (__half2*)xh, nx4);
    cvt_w_kernel<<<(nw4 + 255) / 256, 256>>>((const float4*)Wa, 0, nw4);
    cvt_w_kernel<<<(nw4 + 255) / 256, 256>>>((const float4*)Wi, 1, nw4);

    cudaFuncSetAttribute(gemm_fused_kernel,
                         cudaFuncAttributeMaxDynamicSharedMemorySize,
                         STAGES * STAGE_BYTES);
    dim3 grid(MM / CTA_M, NN / CTA_N);   // (128, 32)
    gemm_fused_kernel<<<grid, 256, STAGES * STAGE_BYTES>>>(ba, bi, gate);

    scan_kernel<<<(BB * II) / 32, 32>>>(out);
}

// round 8
// speedup vs baseline: 2.8970x; 1.0400x over previous
#include <cuda_runtime.h>
#include <cuda_fp16.h>
#include <cstdint>

// Problem dims (fixed per reference setup_inputs)
#define BB 8
#define SS 2048
#define DD 512
#define II 2048
#define MM (BB*SS)   // 16384 rows (b*S+s)
#define NN (2*II)    // 4096 interleaved output cols (even=pa, odd=pi)

#define LN3 1.0986122886681098f

// GEMM tiling
#define CTA_M 128
#define CTA_N 128          // = 64 channels
#define TK 64              // K halves per chunk (128B rows)
#define NCHUNK (DD/TK)     // 8
#define STAGES 3
#define STAGE_BYTES 32768  // x 16K + Wcat 16K
#define W_OFF 16384

// Scratch
__device__ __half  g_xh[(size_t)MM * DD];    // [m, k]
__device__ __half  g_wc[(size_t)NN * DD];    // interleaved [2i+p, k]
__device__ __half2 g_ac[(size_t)MM * II];    // TRANSPOSED [i, m], packed (alpha, drive)

__device__ __forceinline__ uint32_t s2u(const void* p) {
    uint32_t a;
    asm("{ .reg .u64 t; cvta.to.shared.u64 t, %1; cvt.u32.u64 %0, t; }" : "=r"(a) : "l"(p));
    return a;
}

// SW128-style swizzle for 128-byte rows (64 halves)
__device__ __forceinline__ uint32_t swz(uint32_t o) { return o ^ ((o >> 3) & 0x70); }

__device__ __forceinline__ void cpa16(uint32_t dst, const void* src) {
    asm volatile("cp.async.cg.shared.global [%0], [%1], 16;" :: "r"(dst), "l"(src) : "memory");
}
__device__ __forceinline__ void cpa_commit() {
    asm volatile("cp.async.commit_group;" ::: "memory");
}
__device__ __forceinline__ void cpa_wait1() {
    asm volatile("cp.async.wait_group 1;" ::: "memory");
}

__device__ __forceinline__ void ldm_x4(uint32_t* r, uint32_t addr) {
    asm volatile("ldmatrix.sync.aligned.m8n8.x4.shared.b16 {%0,%1,%2,%3}, [%4];"
                 : "=r"(r[0]), "=r"(r[1]), "=r"(r[2]), "=r"(r[3]) : "r"(addr));
}

__device__ __forceinline__ void mma_f16(float* d, const uint32_t* a, uint32_t b0, uint32_t b1) {
    asm volatile(
        "mma.sync.aligned.m16n8k16.row.col.f32.f16.f16.f32 "
        "{%0,%1,%2,%3}, {%4,%5,%6,%7}, {%8,%9}, {%0,%1,%2,%3};\n"
        : "+f"(d[0]), "+f"(d[1]), "+f"(d[2]), "+f"(d[3])
        : "r"(a[0]), "r"(a[1]), "r"(a[2]), "r"(a[3]), "r"(b0), "r"(b1));
}

__device__ __forceinline__ float sigmoidf_(float v) {
    return 1.0f / (1.0f + __expf(-v));
}

// ---- fp32 -> fp16 convert (x) ----
__global__ void cvt_kernel(const float4* __restrict__ src, __half2* __restrict__ dst, int n4)
{
    int i = blockIdx.x * blockDim.x + threadIdx.x;
    if (i < n4) {
        float4 v = src[i];
        dst[2 * i]     = __floats2half2_rn(v.x, v.y);
        dst[2 * i + 1] = __floats2half2_rn(v.z, v.w);
    }
}

// ---- fp32 -> fp16, interleaving W rows: dst row = 2*srcrow + parity ----
__global__ void cvt_w_kernel(const float4* __restrict__ src, int parity, int n4)
{
    int i = blockIdx.x * blockDim.x + threadIdx.x;
    if (i < n4) {
        float4 v = src[i];
        int row = i >> 7;              // DD/4 = 128 float4 per row
        int c4  = i & 127;
        __half2* dst = reinterpret_cast<__half2*>(g_wc) +
                       ((size_t)(2 * row + parity) * (DD / 2) + c4 * 2);
        dst[0] = __floats2half2_rn(v.x, v.y);
        dst[1] = __floats2half2_rn(v.z, v.w);
    }
}

// ---- GEMM: P = x @ Wcat^T (N=4096, interleaved), fused gate epilogue ----
// grid (MM/CTA_M, NN/CTA_N) = (128, 32), 256 threads (8 warps, 2x4), 2 CTAs/SM.
__global__ void __launch_bounds__(256, 2) gemm_fused_kernel(
    const float* __restrict__ ba, const float* __restrict__ bi,
    const float* __restrict__ gate)
{
    extern __shared__ char smem[];
    const uint32_t sbase = s2u(smem);

    const int tid  = threadIdx.x;
    const int wid  = tid >> 5;
    const int lane = tid & 31;
    const int wm   = wid >> 2;          // 0..1 -> 64-row slice
    const int wn   = wid & 3;           // 0..3 -> 32-col slice
    const int g    = lane >> 2;         // 0..7
    const int tg   = lane & 3;          // 0..3
    const int m_blk = blockIdx.x * CTA_M;
    const int n_blk = blockIdx.y * CTA_N;

    float acc[4][4][4];                 // [mt][nt][frag]
    #pragma unroll
    for (int mt = 0; mt < 4; mt++)
        #pragma unroll
        for (int nt = 0; nt < 4; nt++)
            #pragma unroll
            for (int r = 0; r < 4; r++) acc[mt][nt][r] = 0.f;

    // ---- precomputed cp.async dst/src bases (per-thread, chunk-invariant) ----
    uint32_t ldst[8];           // smem dst (stage-0 absolute)
    const __half* lsrc[8];      // global src (chunk-0 absolute)
    {
        #pragma unroll
        for (int t = 0; t < 4; t++) {
            int f = tid + t * 256; int r = f >> 3, c = f & 7;
            ldst[t] = sbase + swz(r * 128 + c * 16);
            lsrc[t] = g_xh + (size_t)(m_blk + r) * DD + c * 8;
        }
        #pragma unroll
        for (int t = 0; t < 4; t++) {
            int f = tid + t * 256; int r = f >> 3, c = f & 7;
            ldst[4 + t] = sbase + W_OFF + swz(r * 128 + c * 16);
            lsrc[4 + t] = g_wc + (size_t)(n_blk + r) * DD + c * 8;
        }
    }
    // issue chunk kc into stage slot; kc & slot must be compile-time constants
    auto issue = [&](int kc, int slot) {
        #pragma unroll
        for (int t = 0; t < 8; t++)
            cpa16(ldst[t] + slot * STAGE_BYTES, lsrc[t] + kc * TK);
        cpa_commit();
    };

    issue(0, 0); issue(1, 1);

    // Absolute swizzled ldsm offsets. swz(row*128 + kb), kb = kk*32 + acol:
    //   = row*128 + ((acol ^ ((row&7)<<4)) ^ kk*32)   (kk bits never carry)
    const int arow = lane & 15;
    const uint32_t acol = (lane >> 4) << 4;   // 0 or 16
    uint32_t aoff[4], boff[2];
    #pragma unroll
    for (int mt = 0; mt < 4; mt++) {
        int row = wm * 64 + mt * 16 + arow;
        aoff[mt] = sbase + row * 128 + (acol ^ ((row & 7) << 4));
    }
    #pragma unroll
    for (int bt = 0; bt < 2; bt++) {
        int row = wn * 32 + bt * 16 + arow;
        boff[bt] = sbase + W_OFF + row * 128 + (acol ^ ((row & 7) << 4));
    }

    #pragma unroll
    for (int kc = 0; kc < NCHUNK; kc++) {
        cpa_wait1();            // group kc complete
        __syncthreads();        // stage-kc visible; prior stage reads done
        if (kc + 2 < NCHUNK) issue(kc + 2, (kc + 2) % STAGES);
        else cpa_commit();      // keep group counting uniform

        const uint32_t so = (kc % STAGES) * STAGE_BYTES;   // immediate under unroll
        #pragma unroll
        for (int kk = 0; kk < 4; kk++) {
            const uint32_t kx = kk * 32;
            uint32_t a[4][4], bw[2][4];
            #pragma unroll
            for (int mt = 0; mt < 4; mt++) ldm_x4(a[mt], (aoff[mt] + so) ^ kx);
            #pragma unroll
            for (int bt = 0; bt < 2; bt++) ldm_x4(bw[bt], (boff[bt] + so) ^ kx);
            #pragma unroll
            for (int mt = 0; mt < 4; mt++)
                #pragma unroll
                for (int nt = 0; nt < 4; nt++) {
                    const int bt = nt >> 1, sub = nt & 1;
                    mma_f16(acc[mt][nt], a[mt], bw[bt][sub], bw[bt][sub + 2]);
                }
        }
    }

    // ---- fused epilogue: (c0,c1)=(pa,pi) of one channel -> half2(alpha,drive) ----
    #pragma unroll
    for (int nt = 0; nt < 4; nt++) {
        const int i = (n_blk >> 1) + wn * 16 + nt * 4 + tg;   // channel index
        const float bav = __ldg(&ba[i]);
        const float biv = __ldg(&bi[i]);
        const float alv = sigmoidf_(__ldg(&gate[i]));
        #pragma unroll
        for (int mt = 0; mt < 4; mt++) {
            const int m0 = m_blk + wm * 64 + mt * 16 + g;
            #pragma unroll
            for (int half = 0; half < 2; half++) {            // rows g, g+8
                const int m = m0 + half * 8;
                float pa = acc[mt][nt][2 * half]     + bav;
                float pi = acc[mt][nt][2 * half + 1] + biv;
                float rg = sigmoidf_(pa);
                float ig = sigmoidf_(pi);
                float aa = alv * __expf(-LN3 * rg);
                float dr = sqrtf(fmaxf(1.0f - aa * aa, 0.0f)) * (ig * pi);
                g_ac[(size_t)i * MM + m] = __floats2half2_rn(aa, dr);
            }
        }
    }
}

// ---- Sequential scan per (b,i): contiguous uint4 reads of packed (a,c) ----
// 64 s-steps per iter = 16 uint4 (256B) prefetched -> ~4MB chip-wide in flight.
__global__ void __launch_bounds__(32) scan_kernel(float* __restrict__ out)
{
    const int idx = blockIdx.x * 32 + threadIdx.x;
    const int b = idx >> 11;
    const int i = idx & (II - 1);
    const uint4* acp = reinterpret_cast<const uint4*>(g_ac + (size_t)i * MM + b * SS);
    float* op = out + (size_t)b * SS * II + i;

    uint4 U[16], P[16];
    #pragma unroll
    for (int j = 0; j < 16; j++) U[j] = acp[j];

    float h = 0.0f;
    for (int s0 = 0; s0 < SS; s0 += 64) {
        if (s0 + 64 < SS) {
            const int q = (s0 >> 2) + 16;
            #pragma unroll
            for (int j = 0; j < 16; j++) P[j] = acp[q + j];
        }
        #pragma unroll
        for (int j = 0; j < 16; j++) {
            const uint32_t w[4] = { U[j].x, U[j].y, U[j].z, U[j].w };
            #pragma unroll
            for (int k = 0; k < 4; k++) {
                float2 p = __half22float2(*reinterpret_cast<const __half2*>(&w[k]));
                h = fmaf(p.x, h, p.y);
                op[(size_t)(s0 + j * 4 + k) * II] = h;
            }
        }
        #pragma unroll
        for (int j = 0; j < 16; j++) U[j] = P[j];
    }
}

extern "C" void kernel_launch(void* const* d_in, const int* in_sizes, int n_in,
                              void* d_out, int out_size)
{
    const float* x    = (const float*)d_in[0];
    const float* Wa   = (const float*)d_in[1];
    const float* ba   = (const float*)d_in[2];
    const float* Wi   = (const float*)d_in[3];
    const float* bi   = (const float*)d_in[4];
    const float* gate = (const float*)d_in[5];
    float* out = (float*)d_out;

    __half* xh; cudaGetSymbolAddress((void**)&xh, g_xh);

    const int nx4 = MM * DD / 4;
    const int nw4 = II * DD / 4;
    cvt_kernel<<<(nx4 + 255) / 256, 256>>>((const float4*)x, (__half2*)xh, nx4);
    cvt_w_kernel<<<(nw4 + 255) / 256, 256>>>((const float4*)Wa, 0, nw4);
    cvt_w_kernel<<<(nw4 + 255) / 256, 256>>>((const float4*)Wi, 1, nw4);

    cudaFuncSetAttribute(gemm_fused_kernel,
                         cudaFuncAttributeMaxDynamicSharedMemorySize,
                         STAGES * STAGE_BYTES);
    dim3 grid(MM / CTA_M, NN / CTA_N);   // (128, 32)
    gemm_fused_kernel<<<grid, 256, STAGES * STAGE_BYTES>>>(ba, bi, gate);

    scan_kernel<<<(BB * II) / 32, 32>>>(out);
}

// round 9
// speedup vs baseline: 2.9549x; 1.0200x over previous
#include <cuda_runtime.h>
#include <cuda_fp16.h>
#include <cstdint>

// Problem dims (fixed per reference setup_inputs)
#define BB 8
#define SS 2048
#define DD 512
#define II 2048
#define MM (BB*SS)   // 16384 rows (b*S+s)
#define NN (2*II)    // 4096 interleaved output cols (even=pa, odd=pi)

#define LN3 1.0986122886681098f

// GEMM tiling
#define CTA_M 128
#define CTA_N 128          // = 64 channels
#define TK 64              // K halves per chunk (128B rows)
#define NCHUNK (DD/TK)     // 8
#define STAGES 3
#define STAGE_BYTES 32768  // x 16K + Wcat 16K
#define W_OFF 16384

// Scratch
__device__ __half  g_xh[(size_t)MM * DD];    // [m, k]
__device__ __half  g_wc[(size_t)NN * DD];    // interleaved [2i+p, k]
__device__ __half2 g_ac[(size_t)MM * II];    // TRANSPOSED [i, m], packed (alpha, drive)

__device__ __forceinline__ uint32_t s2u(const void* p) {
    uint32_t a;
    asm("{ .reg .u64 t; cvta.to.shared.u64 t, %1; cvt.u32.u64 %0, t; }" : "=r"(a) : "l"(p));
    return a;
}

// SW128-style swizzle for 128-byte rows (64 halves)
__device__ __forceinline__ uint32_t swz(uint32_t o) { return o ^ ((o >> 3) & 0x70); }

__device__ __forceinline__ void cpa16(uint32_t dst, const void* src) {
    asm volatile("cp.async.cg.shared.global [%0], [%1], 16;" :: "r"(dst), "l"(src) : "memory");
}
__device__ __forceinline__ void cpa_commit() {
    asm volatile("cp.async.commit_group;" ::: "memory");
}
__device__ __forceinline__ void cpa_wait1() {
    asm volatile("cp.async.wait_group 1;" ::: "memory");
}

__device__ __forceinline__ void ldm_x4(uint32_t* r, uint32_t addr) {
    asm volatile("ldmatrix.sync.aligned.m8n8.x4.shared.b16 {%0,%1,%2,%3}, [%4];"
                 : "=r"(r[0]), "=r"(r[1]), "=r"(r[2]), "=r"(r[3]) : "r"(addr));
}

__device__ __forceinline__ void mma_f16(float* d, const uint32_t* a, uint32_t b0, uint32_t b1) {
    asm volatile(
        "mma.sync.aligned.m16n8k16.row.col.f32.f16.f16.f32 "
        "{%0,%1,%2,%3}, {%4,%5,%6,%7}, {%8,%9}, {%0,%1,%2,%3};\n"
        : "+f"(d[0]), "+f"(d[1]), "+f"(d[2]), "+f"(d[3])
        : "r"(a[0]), "r"(a[1]), "r"(a[2]), "r"(a[3]), "r"(b0), "r"(b1));
}

__device__ __forceinline__ float sigmoidf_(float v) {
    return 1.0f / (1.0f + __expf(-v));
}

// ---- fp32 -> fp16 convert (x) ----
__global__ void cvt_kernel(const float4* __restrict__ src, __half2* __restrict__ dst, int n4)
{
    int i = blockIdx.x * blockDim.x + threadIdx.x;
    if (i < n4) {
        float4 v = src[i];
        dst[2 * i]     = __floats2half2_rn(v.x, v.y);
        dst[2 * i + 1] = __floats2half2_rn(v.z, v.w);
    }
}

// ---- fp32 -> fp16, interleaving W rows: dst row = 2*srcrow + parity ----
__global__ void cvt_w_kernel(const float4* __restrict__ src, int parity, int n4)
{
    int i = blockIdx.x * blockDim.x + threadIdx.x;
    if (i < n4) {
        float4 v = src[i];
        int row = i >> 7;              // DD/4 = 128 float4 per row
        int c4  = i & 127;
        __half2* dst = reinterpret_cast<__half2*>(g_wc) +
                       ((size_t)(2 * row + parity) * (DD / 2) + c4 * 2);
        dst[0] = __floats2half2_rn(v.x, v.y);
        dst[1] = __floats2half2_rn(v.z, v.w);
    }
}

// ---- GEMM: P = x @ Wcat^T (N=4096, interleaved), fused gate epilogue ----
// grid (MM/CTA_M, NN/CTA_N) = (128, 32), 256 threads (8 warps, 2x4), 2 CTAs/SM.
__global__ void __launch_bounds__(256, 2) gemm_fused_kernel(
    const float* __restrict__ ba, const float* __restrict__ bi,
    const float* __restrict__ gate)
{
    extern __shared__ char smem[];
    const uint32_t sbase = s2u(smem);

    const int tid  = threadIdx.x;
    const int wid  = tid >> 5;
    const int lane = tid & 31;
    const int wm   = wid >> 2;          // 0..1 -> 64-row slice
    const int wn   = wid & 3;           // 0..3 -> 32-col slice
    const int g    = lane >> 2;         // 0..7
    const int tg   = lane & 3;          // 0..3
    const int m_blk = blockIdx.x * CTA_M;
    const int n_blk = blockIdx.y * CTA_N;

    float acc[4][4][4];                 // [mt][nt][frag]
    #pragma unroll
    for (int mt = 0; mt < 4; mt++)
        #pragma unroll
        for (int nt = 0; nt < 4; nt++)
            #pragma unroll
            for (int r = 0; r < 4; r++) acc[mt][nt][r] = 0.f;

    // ---- base-register + immediate cp.async addressing ----
    // thread (r0 = tid>>3, c = tid&7); variant t adds 32 rows:
    //   smem: +t*4096 bytes (swizzle bits untouched: r&7 invariant)
    //   gmem: +t*32*DD halves = +32768 B;  chunk kc adds kc*TK halves = +128 B
    const int r0 = tid >> 3, c0 = tid & 7;
    const uint32_t xs0 = sbase + swz(r0 * 128 + c0 * 16);
    const uint32_t ws0 = sbase + W_OFF + swz(r0 * 128 + c0 * 16);
    const __half* xg0 = g_xh + (size_t)(m_blk + r0) * DD + c0 * 8;
    const __half* wg0 = g_wc + (size_t)(n_blk + r0) * DD + c0 * 8;

    auto issue = [&](int kc, int slot) {   // kc, slot compile-time under unroll
        #pragma unroll
        for (int t = 0; t < 4; t++)
            cpa16(xs0 + slot * STAGE_BYTES + t * 4096,
                  xg0 + kc * TK + t * 32 * DD);
        #pragma unroll
        for (int t = 0; t < 4; t++)
            cpa16(ws0 + slot * STAGE_BYTES + t * 4096,
                  wg0 + kc * TK + t * 32 * DD);
        cpa_commit();
    };

    issue(0, 0); issue(1, 1);

    // Absolute swizzled ldsm offsets. swz(row*128 + kb), kb = kk*32 + acol:
    //   = row*128 + ((acol ^ ((row&7)<<4)) ^ kk*32)   (kk bits never carry)
    const int arow = lane & 15;
    const uint32_t acol = (lane >> 4) << 4;   // 0 or 16
    uint32_t aoff[4], boff[2];
    #pragma unroll
    for (int mt = 0; mt < 4; mt++) {
        int row = wm * 64 + mt * 16 + arow;
        aoff[mt] = sbase + row * 128 + (acol ^ ((row & 7) << 4));
    }
    #pragma unroll
    for (int bt = 0; bt < 2; bt++) {
        int row = wn * 32 + bt * 16 + arow;
        boff[bt] = sbase + W_OFF + row * 128 + (acol ^ ((row & 7) << 4));
    }

    #pragma unroll
    for (int kc = 0; kc < NCHUNK; kc++) {
        cpa_wait1();            // group kc complete
        __syncthreads();        // stage-kc visible; prior stage reads done
        if (kc + 2 < NCHUNK) issue(kc + 2, (kc + 2) % STAGES);
        else cpa_commit();      // keep group counting uniform

        const uint32_t so = (kc % STAGES) * STAGE_BYTES;   // immediate under unroll

        // register double-buffered fragments
        uint32_t a[2][4][4], bw[2][2][4];
        #pragma unroll
        for (int mt = 0; mt < 4; mt++) ldm_x4(a[0][mt], aoff[mt] + so);
        #pragma unroll
        for (int bt = 0; bt < 2; bt++) ldm_x4(bw[0][bt], boff[bt] + so);

        #pragma unroll
        for (int kk = 0; kk < 4; kk++) {
            const int cur = kk & 1, nxt = cur ^ 1;
            if (kk < 3) {
                const uint32_t kx = (kk + 1) * 32;
                #pragma unroll
                for (int mt = 0; mt < 4; mt++) ldm_x4(a[nxt][mt], (aoff[mt] + so) ^ kx);
                #pragma unroll
                for (int bt = 0; bt < 2; bt++) ldm_x4(bw[nxt][bt], (boff[bt] + so) ^ kx);
            }
            #pragma unroll
            for (int mt = 0; mt < 4; mt++)
                #pragma unroll
                for (int nt = 0; nt < 4; nt++) {
                    const int bt = nt >> 1, sub = nt & 1;
                    mma_f16(acc[mt][nt], a[cur][mt], bw[cur][bt][sub], bw[cur][bt][sub + 2]);
                }
        }
    }

    // ---- fused epilogue: (c0,c1)=(pa,pi) of one channel -> half2(alpha,drive) ----
    #pragma unroll
    for (int nt = 0; nt < 4; nt++) {
        const int i = (n_blk >> 1) + wn * 16 + nt * 4 + tg;   // channel index
        const float bav = __ldg(&ba[i]);
        const float biv = __ldg(&bi[i]);
        const float alv = sigmoidf_(__ldg(&gate[i]));
        #pragma unroll
        for (int mt = 0; mt < 4; mt++) {
            const int m0 = m_blk + wm * 64 + mt * 16 + g;
            #pragma unroll
            for (int half = 0; half < 2; half++) {            // rows g, g+8
                const int m = m0 + half * 8;
                float pa = acc[mt][nt][2 * half]     + bav;
                float pi = acc[mt][nt][2 * half + 1] + biv;
                float rg = sigmoidf_(pa);
                float ig = sigmoidf_(pi);
                float aa = alv * __expf(-LN3 * rg);
                float dr = sqrtf(fmaxf(1.0f - aa * aa, 0.0f)) * (ig * pi);
                g_ac[(size_t)i * MM + m] = __floats2half2_rn(aa, dr);
            }
        }
    }
}

// ---- Sequential scan per (b,i): contiguous uint4 reads of packed (a,c) ----
// 64 s-steps per iter = 16 uint4 (256B) prefetched -> ~4MB chip-wide in flight.
__global__ void __launch_bounds__(32) scan_kernel(float* __restrict__ out)
{
    const int idx = blockIdx.x * 32 + threadIdx.x;
    const int b = idx >> 11;
    const int i = idx & (II - 1);
    const uint4* acp = reinterpret_cast<const uint4*>(g_ac + (size_t)i * MM + b * SS);
    float* op = out + (size_t)b * SS * II + i;

    uint4 U[16], P[16];
    #pragma unroll
    for (int j = 0; j < 16; j++) U[j] = acp[j];

    float h = 0.0f;
    for (int s0 = 0; s0 < SS; s0 += 64) {
        if (s0 + 64 < SS) {
            const int q = (s0 >> 2) + 16;
            #pragma unroll
            for (int j = 0; j < 16; j++) P[j] = acp[q + j];
        }
        #pragma unroll
        for (int j = 0; j < 16; j++) {
            const uint32_t w[4] = { U[j].x, U[j].y, U[j].z, U[j].w };
            #pragma unroll
            for (int k = 0; k < 4; k++) {
                float2 p = __half22float2(*reinterpret_cast<const __half2*>(&w[k]));
                h = fmaf(p.x, h, p.y);
                op[(size_t)(s0 + j * 4 + k) * II] = h;
            }
        }
        #pragma unroll
        for (int j = 0; j < 16; j++) U[j] = P[j];
    }
}

extern "C" void kernel_launch(void* const* d_in, const int* in_sizes, int n_in,
                              void* d_out, int out_size)
{
    const float* x    = (const float*)d_in[0];
    const float* Wa   = (const float*)d_in[1];
    const float* ba   = (const float*)d_in[2];
    const float* Wi   = (const float*)d_in[3];
    const float* bi   = (const float*)d_in[4];
    const float* gate = (const float*)d_in[5];
    float* out = (float*)d_out;

    __half* xh; cudaGetSymbolAddress((void**)&xh, g_xh);

    const int nx4 = MM * DD / 4;
    const int nw4 = II * DD / 4;
    cvt_kernel<<<(nx4 + 255) / 256, 256>>>((const float4*)x, (__half2*)xh, nx4);
    cvt_w_kernel<<<(nw4 + 255) / 256, 256>>>((const float4*)Wa, 0, nw4);
    cvt_w_kernel<<<(nw4 + 255) / 256, 256>>>((const float4*)Wi, 1, nw4);

    cudaFuncSetAttribute(gemm_fused_kernel,
                         cudaFuncAttributeMaxDynamicSharedMemorySize,
                         STAGES * STAGE_BYTES);
    dim3 grid(MM / CTA_M, NN / CTA_N);   // (128, 32)
    gemm_fused_kernel<<<grid, 256, STAGES * STAGE_BYTES>>>(ba, bi, gate);

    scan_kernel<<<(BB * II) / 32, 32>>>(out);
}